// round 2
// baseline (speedup 1.0000x reference)
#include <cuda_runtime.h>

// DIN-style attention, algebraically refactored:
//   comb@W1 = fact @ A_b + qW_b,  A_b[d,h] = W1a - W1d + q[d]*W1c (per batch)
// One CTA per batch b. Thread t scores history step t. fp32 with packed
// fma.rn.f32x2 (FFMA2). Layers 1+2 fused per 40-wide h-half to cap register
// liveness (~96 regs peak, no spills at launch_bounds(224,2)).

typedef unsigned long long ull;

#define TB 224          // threads per block (7 warps; 200 active for t-loop)
#define T_LEN 200
#define D_DIM 64
#define H1 80
#define HHALF 40
#define H2 40
#define FACT_STRIDE 65  // odd stride -> conflict-free lane-per-t smem reads

struct __align__(16) Smem {
    float A[D_DIM * H1];            // 20480 B  combined layer-1 weight (per b)
    float fact[T_LEN * FACT_STRIDE];// 52000 B  fact tile, padded rows
    float W2s[H1 * H2];             // 12800 B
    float qW[H1];                   // per-b layer-1 bias (b1 + q-path)
    float q[D_DIM];
    float b2s[H2];
    float W3s[H2];
    float b3s;
    float red[3];
    float scores[T_LEN];
    float partial[128];
};

static __device__ __forceinline__ ull fma2(ull a, ull b, ull c) {
    ull d;
    asm("fma.rn.f32x2 %0, %1, %2, %3;" : "=l"(d) : "l"(a), "l"(b), "l"(c));
    return d;
}
static __device__ __forceinline__ ull pack2(float x, float y) {
    ull r;
    asm("mov.b64 %0, {%1, %2};" : "=l"(r) : "f"(x), "f"(y));
    return r;
}
static __device__ __forceinline__ void unpack2(ull v, float& x, float& y) {
    asm("mov.b64 {%0, %1}, %2;" : "=f"(x), "=f"(y) : "l"(v));
}
static __device__ __forceinline__ float sigm(float x) {
    return __fdividef(1.0f, 1.0f + __expf(-x));
}

__global__ __launch_bounds__(TB, 2)
void din_attn_kernel(const float* __restrict__ query,
                     const float* __restrict__ fact,
                     const int*   __restrict__ mask,
                     const float* __restrict__ W1,
                     const float* __restrict__ b1,
                     const float* __restrict__ W2,
                     const float* __restrict__ b2,
                     const float* __restrict__ W3,
                     const float* __restrict__ b3,
                     float* __restrict__ out)
{
    extern __shared__ Smem smem_raw[];
    Smem* sm = smem_raw;
    const int tid = threadIdx.x;
    const int b   = blockIdx.x;

    if (tid < D_DIM) sm->q[tid] = query[b * D_DIM + tid];
    __syncthreads();

    // ---- Prologue: role-split warps. Warps 0-3 stage fact; warps 4-6 build
    // ---- the per-b combined weights (A, qW) and stage W2/b2/W3/b3.
    if (tid < 128) {
        const float4* src = (const float4*)(fact + (size_t)b * (T_LEN * D_DIM));
        for (int i = tid; i < T_LEN * D_DIM / 4; i += 128) {
            float4 v = src[i];
            int t  = i >> 4;            // 16 float4 per row of 64
            int d4 = (i & 15) << 2;
            float* dst = &sm->fact[t * FACT_STRIDE + d4];
            dst[0] = v.x; dst[1] = v.y; dst[2] = v.z; dst[3] = v.w;
        }
    } else {
        const int id = tid - 128;       // 0..95
        // A[d,h] = W1[d,h] - W1[192+d,h] + q[d]*W1[128+d,h]
        for (int i = id; i < D_DIM * H1; i += 96) {
            int d = i / H1, h = i - d * H1;
            float wa = W1[d * H1 + h];
            float wc = W1[(128 + d) * H1 + h];
            float wd = W1[(192 + d) * H1 + h];
            sm->A[i] = wa - wd + sm->q[d] * wc;
        }
        // qW[h] = b1[h] + sum_d q[d]*(W1[64+d,h] + W1[192+d,h])
        if (id < H1) {
            float a = b1[id];
            #pragma unroll 4
            for (int d = 0; d < D_DIM; d++)
                a += sm->q[d] * (W1[(64 + d) * H1 + id] + W1[(192 + d) * H1 + id]);
            sm->qW[id] = a;
        }
        for (int i = id; i < H1 * H2; i += 96) sm->W2s[i] = W2[i];
        if (id < H2) sm->b2s[id] = b2[id];
        if (id < H2) sm->W3s[id] = W3[id];
        if (id == 95) sm->b3s = b3[0];
    }
    __syncthreads();

    const int t = tid;
    float score = 0.0f;
    int   m     = 0;
    float e     = 0.0f;

    if (t < T_LEN) {
        m = mask[b * T_LEN + t];
        const float* fr = &sm->fact[t * FACT_STRIDE];

        // ---- Layer 2 accumulators persist across both h-halves.
        ull acc2[H2 / 2];
        const ull* b2p = (const ull*)sm->b2s;
        #pragma unroll
        for (int i = 0; i < H2 / 2; i++) acc2[i] = b2p[i];

        // ---- Fused layers 1+2, one 40-wide h-half at a time (caps liveness).
        #pragma unroll
        for (int half = 0; half < 2; half++) {
            const int h0 = half * HHALF;

            // Layer 1 partial: acc[h0..h0+40) = qW + fact_t @ A[:, h0..h0+40)
            ull acc[HHALF / 2];
            const ull* qwp = (const ull*)(sm->qW + h0);
            #pragma unroll
            for (int i = 0; i < HHALF / 2; i++) acc[i] = qwp[i];

            #pragma unroll 2
            for (int d = 0; d < D_DIM; d++) {
                float f = fr[d];
                ull f2 = pack2(f, f);
                const ulonglong2* row =
                    (const ulonglong2*)(sm->A + d * H1 + h0);
                #pragma unroll
                for (int j = 0; j < HHALF / 4; j++) {
                    ulonglong2 a = row[j];
                    acc[2 * j]     = fma2(f2, a.x, acc[2 * j]);
                    acc[2 * j + 1] = fma2(f2, a.y, acc[2 * j + 1]);
                }
            }

            // Sigmoid + immediate drain into layer-2 accumulators.
            #pragma unroll
            for (int i = 0; i < HHALF / 2; i++) {
                float x, y; unpack2(acc[i], x, y);
                ull g0 = pack2(sigm(x), sigm(x));
                ull g1 = pack2(sigm(y), sigm(y));
                const ulonglong2* r0 =
                    (const ulonglong2*)(sm->W2s + (h0 + 2 * i) * H2);
                const ulonglong2* r1 =
                    (const ulonglong2*)(sm->W2s + (h0 + 2 * i + 1) * H2);
                #pragma unroll
                for (int j = 0; j < H2 / 4; j++) {
                    ulonglong2 w0 = r0[j];
                    ulonglong2 w1 = r1[j];
                    acc2[2 * j]     = fma2(g0, w0.x, acc2[2 * j]);
                    acc2[2 * j + 1] = fma2(g0, w0.y, acc2[2 * j + 1]);
                    acc2[2 * j]     = fma2(g1, w1.x, acc2[2 * j]);
                    acc2[2 * j + 1] = fma2(g1, w1.y, acc2[2 * j + 1]);
                }
            }
        }

        // ---- Layer 3: score = sigmoid(h2) @ W3 + b3
        ull sp = 0ull;
        const ull* W3p = (const ull*)sm->W3s;
        #pragma unroll
        for (int i = 0; i < H2 / 2; i++) {
            float x, y; unpack2(acc2[i], x, y);
            sp = fma2(pack2(sigm(x), sigm(y)), W3p[i], sp);
        }
        float sx, sy; unpack2(sp, sx, sy);
        score = sx + sy + sm->b3s;
        if (m != 1) score = -2147483648.0f;   // NEG_BIG = -2^31 exactly
        sm->scores[t] = score;
    }
    __syncthreads();

    // ---- Masked softmax over T (block reductions by warp 0)
    if (tid < 32) {
        float v = -3.4e38f;
        for (int i = tid; i < T_LEN; i += 32) v = fmaxf(v, sm->scores[i]);
        #pragma unroll
        for (int o = 16; o; o >>= 1) v = fmaxf(v, __shfl_xor_sync(0xffffffffu, v, o));
        if (tid == 0) sm->red[0] = v;
    }
    __syncthreads();
    if (t < T_LEN) {
        e = __expf(score - sm->red[0]);   // masked: exp(-huge) -> 0
        sm->scores[t] = e;
    }
    __syncthreads();
    if (tid < 32) {
        float v = 0.0f;
        for (int i = tid; i < T_LEN; i += 32) v += sm->scores[i];
        #pragma unroll
        for (int o = 16; o; o >>= 1) v += __shfl_xor_sync(0xffffffffu, v, o);
        if (tid == 0) sm->red[1] = __fdividef(1.0f, v);
    }
    __syncthreads();
    if (t < T_LEN) sm->scores[t] = e * sm->red[1] * (float)m;
    __syncthreads();

    // ---- out[b,d] = sum_t p[t] * fact[t,d]  (two half-T partials)
    if (tid < 128) {
        int d = tid & 63, half = tid >> 6;
        float acc = 0.0f;
        int t0 = half * (T_LEN / 2);
        for (int tt = t0; tt < t0 + T_LEN / 2; tt++)
            acc += sm->scores[tt] * sm->fact[tt * FACT_STRIDE + d];
        sm->partial[tid] = acc;
    }
    __syncthreads();
    if (tid < D_DIM)
        out[b * D_DIM + tid] = sm->partial[tid] + sm->partial[64 + tid];
}

extern "C" void kernel_launch(void* const* d_in, const int* in_sizes, int n_in,
                              void* d_out, int out_size)
{
    const float* query = (const float*)d_in[0];
    const float* fact  = (const float*)d_in[1];
    const int*   mask  = (const int*)  d_in[2];
    const float* W1    = (const float*)d_in[3];
    const float* b1    = (const float*)d_in[4];
    const float* W2    = (const float*)d_in[5];
    const float* b2    = (const float*)d_in[6];
    const float* W3    = (const float*)d_in[7];
    const float* b3    = (const float*)d_in[8];
    float* out = (float*)d_out;

    const int B = in_sizes[0] / D_DIM;           // 4096
    const int smem_bytes = (int)sizeof(Smem);    // ~87.5 KB (needs opt-in)
    cudaFuncSetAttribute(din_attn_kernel,
                         cudaFuncAttributeMaxDynamicSharedMemorySize, smem_bytes);
    din_attn_kernel<<<B, TB, smem_bytes>>>(query, fact, mask, W1, b1, W2, b2,
                                           W3, b3, out);
}

// round 8
// speedup vs baseline: 1.0351x; 1.0351x over previous
#include <cuda_runtime.h>

// DIN-style attention, algebraically refactored:
//   comb@W1 = fact @ A_b + qW_b,  A_b[d,h] = W1a - W1d + q[d]*W1c (per batch)
// R2: t-blocked — each thread scores TWO history steps (t, t+100) so every
// broadcast weight LDS.128 feeds 2x the FMAs (L1 pipe was binding at 75.8%).
// fact rows read as float4 with stride 68 (==4 mod 32: conflict-free LDS.128).
// (R7 = R2 resubmitted verbatim; R2-R6 benches were broker acquisition
// timeouts — this design has never reached hardware.)

typedef unsigned long long ull;

#define TB 128
#define T_LEN 200
#define THALF 100       // threads 0..99 handle t and t+100
#define D_DIM 64
#define H1 80
#define HQ 20           // h-chunk width (layer-1 partial, then drained)
#define H2 40
#define FACT_STRIDE 68  // ==4 mod 32 -> conflict-free float4 lane-per-t reads

struct __align__(16) Smem {
    float A[D_DIM * H1];             // 20480 B  combined layer-1 weight (per b)
    float fact[T_LEN * FACT_STRIDE]; // 54400 B  fact tile, padded rows
    float W2s[H1 * H2];              // 12800 B
    float qW[H1];                    // per-b layer-1 bias (b1 + q-path)
    float q[D_DIM];
    float b2s[H2];
    float W3s[H2];
    float b3s;
    float red[2];
    float scores[T_LEN];
    float partial[128];
};

static __device__ __forceinline__ ull fma2(ull a, ull b, ull c) {
    ull d;
    asm("fma.rn.f32x2 %0, %1, %2, %3;" : "=l"(d) : "l"(a), "l"(b), "l"(c));
    return d;
}
static __device__ __forceinline__ ull pack2(float x, float y) {
    ull r;
    asm("mov.b64 %0, {%1, %2};" : "=l"(r) : "f"(x), "f"(y));
    return r;
}
static __device__ __forceinline__ void unpack2(ull v, float& x, float& y) {
    asm("mov.b64 {%0, %1}, %2;" : "=f"(x), "=f"(y) : "l"(v));
}
static __device__ __forceinline__ float sigm(float x) {
    return __fdividef(1.0f, 1.0f + __expf(-x));
}

__global__ __launch_bounds__(TB, 2)
void din_attn_kernel(const float* __restrict__ query,
                     const float* __restrict__ fact,
                     const int*   __restrict__ mask,
                     const float* __restrict__ W1,
                     const float* __restrict__ b1,
                     const float* __restrict__ W2,
                     const float* __restrict__ b2,
                     const float* __restrict__ W3,
                     const float* __restrict__ b3,
                     float* __restrict__ out)
{
    extern __shared__ Smem smem_raw[];
    Smem* sm = smem_raw;
    const int tid = threadIdx.x;
    const int b   = blockIdx.x;

    if (tid < D_DIM) sm->q[tid] = query[b * D_DIM + tid];
    __syncthreads();

    // ---- Prologue: threads 0-47 stage fact; threads 48-127 build weights.
    if (tid < 48) {
        const float4* src = (const float4*)(fact + (size_t)b * (T_LEN * D_DIM));
        for (int i = tid; i < T_LEN * D_DIM / 4; i += 48) {
            float4 v = src[i];
            int t  = i >> 4;            // 16 float4 per row of 64
            int d4 = (i & 15) << 2;
            float* dst = &sm->fact[t * FACT_STRIDE + d4];
            dst[0] = v.x; dst[1] = v.y; dst[2] = v.z; dst[3] = v.w;
        }
    } else {
        const int id = tid - 48;        // 0..79
        // A[d,h] = W1[d,h] - W1[192+d,h] + q[d]*W1[128+d,h]
        for (int i = id; i < D_DIM * H1; i += 80) {
            int d = i / H1, h = i - d * H1;
            float wa = W1[d * H1 + h];
            float wc = W1[(128 + d) * H1 + h];
            float wd = W1[(192 + d) * H1 + h];
            sm->A[i] = wa - wd + sm->q[d] * wc;
        }
        // qW[h] = b1[h] + sum_d q[d]*(W1[64+d,h] + W1[192+d,h])
        {
            float a = b1[id];
            #pragma unroll 4
            for (int d = 0; d < D_DIM; d++)
                a += sm->q[d] * (W1[(64 + d) * H1 + id] + W1[(192 + d) * H1 + id]);
            sm->qW[id] = a;
        }
        for (int i = id; i < H1 * H2; i += 80) sm->W2s[i] = W2[i];
        if (id < H2) sm->b2s[id] = b2[id];
        if (id < H2) sm->W3s[id] = W3[id];
        if (id == 79) sm->b3s = b3[0];
    }
    __syncthreads();

    float score0 = 0.0f, score1 = 0.0f;
    int   m0 = 0, m1 = 0;
    float e0 = 0.0f, e1 = 0.0f;

    if (tid < THALF) {
        const int t0 = tid, t1 = tid + THALF;
        m0 = mask[b * T_LEN + t0];
        m1 = mask[b * T_LEN + t1];
        const float* fr0 = &sm->fact[t0 * FACT_STRIDE];
        const float* fr1 = &sm->fact[t1 * FACT_STRIDE];

        // ---- Layer-2 accumulators persist across all 4 h-chunks (2 t's).
        ull acc2_0[H2 / 2], acc2_1[H2 / 2];
        const ull* b2p = (const ull*)sm->b2s;
        #pragma unroll
        for (int i = 0; i < H2 / 2; i++) { acc2_0[i] = b2p[i]; acc2_1[i] = b2p[i]; }

        #pragma unroll
        for (int c = 0; c < H1 / HQ; c++) {
            const int h0 = c * HQ;

            // Layer-1 partial over this 20-wide h-chunk, both t's.
            ull a1_0[HQ / 2], a1_1[HQ / 2];
            const ull* qwp = (const ull*)(sm->qW + h0);
            #pragma unroll
            for (int i = 0; i < HQ / 2; i++) { a1_0[i] = qwp[i]; a1_1[i] = qwp[i]; }

            #pragma unroll 2
            for (int d4 = 0; d4 < D_DIM / 4; d4++) {
                float4 f0 = *(const float4*)(fr0 + 4 * d4);
                float4 f1 = *(const float4*)(fr1 + 4 * d4);
                const float fa[4] = {f0.x, f0.y, f0.z, f0.w};
                const float fb[4] = {f1.x, f1.y, f1.z, f1.w};
                #pragma unroll
                for (int dd = 0; dd < 4; dd++) {
                    ull p0 = pack2(fa[dd], fa[dd]);
                    ull p1 = pack2(fb[dd], fb[dd]);
                    const ulonglong2* row =
                        (const ulonglong2*)(sm->A + (4 * d4 + dd) * H1 + h0);
                    #pragma unroll
                    for (int j = 0; j < HQ / 4; j++) {
                        ulonglong2 a = row[j];     // one load feeds both t's
                        a1_0[2 * j]     = fma2(p0, a.x, a1_0[2 * j]);
                        a1_0[2 * j + 1] = fma2(p0, a.y, a1_0[2 * j + 1]);
                        a1_1[2 * j]     = fma2(p1, a.x, a1_1[2 * j]);
                        a1_1[2 * j + 1] = fma2(p1, a.y, a1_1[2 * j + 1]);
                    }
                }
            }

            // Sigmoid + drain chunk into layer-2 accumulators (both t's).
            #pragma unroll
            for (int i = 0; i < HQ / 2; i++) {
                float x0, y0, x1, y1;
                unpack2(a1_0[i], x0, y0);
                unpack2(a1_1[i], x1, y1);
                ull g00 = pack2(sigm(x0), sigm(x0));   // t0, h even
                ull g01 = pack2(sigm(y0), sigm(y0));   // t0, h odd
                ull g10 = pack2(sigm(x1), sigm(x1));   // t1, h even
                ull g11 = pack2(sigm(y1), sigm(y1));   // t1, h odd
                const ulonglong2* r0 =
                    (const ulonglong2*)(sm->W2s + (h0 + 2 * i) * H2);
                const ulonglong2* r1 =
                    (const ulonglong2*)(sm->W2s + (h0 + 2 * i + 1) * H2);
                #pragma unroll
                for (int j = 0; j < H2 / 4; j++) {
                    ulonglong2 w0 = r0[j];
                    ulonglong2 w1 = r1[j];
                    acc2_0[2 * j]     = fma2(g00, w0.x, acc2_0[2 * j]);
                    acc2_0[2 * j + 1] = fma2(g00, w0.y, acc2_0[2 * j + 1]);
                    acc2_0[2 * j]     = fma2(g01, w1.x, acc2_0[2 * j]);
                    acc2_0[2 * j + 1] = fma2(g01, w1.y, acc2_0[2 * j + 1]);
                    acc2_1[2 * j]     = fma2(g10, w0.x, acc2_1[2 * j]);
                    acc2_1[2 * j + 1] = fma2(g10, w0.y, acc2_1[2 * j + 1]);
                    acc2_1[2 * j]     = fma2(g11, w1.x, acc2_1[2 * j]);
                    acc2_1[2 * j + 1] = fma2(g11, w1.y, acc2_1[2 * j + 1]);
                }
            }
        }

        // ---- Layer 3: score = sigmoid(h2) @ W3 + b3 (both t's)
        ull sp0 = 0ull, sp1 = 0ull;
        const ull* W3p = (const ull*)sm->W3s;
        #pragma unroll
        for (int i = 0; i < H2 / 2; i++) {
            float x0, y0, x1, y1;
            unpack2(acc2_0[i], x0, y0);
            unpack2(acc2_1[i], x1, y1);
            ull w = W3p[i];
            sp0 = fma2(pack2(sigm(x0), sigm(y0)), w, sp0);
            sp1 = fma2(pack2(sigm(x1), sigm(y1)), w, sp1);
        }
        float sx, sy;
        unpack2(sp0, sx, sy);
        score0 = sx + sy + sm->b3s;
        unpack2(sp1, sx, sy);
        score1 = sx + sy + sm->b3s;
        if (m0 != 1) score0 = -2147483648.0f;   // NEG_BIG = -2^31 exactly
        if (m1 != 1) score1 = -2147483648.0f;
        sm->scores[t0] = score0;
        sm->scores[t1] = score1;
    }
    __syncthreads();

    // ---- Masked softmax over T (block reductions by warp 0)
    if (tid < 32) {
        float v = -3.4e38f;
        for (int i = tid; i < T_LEN; i += 32) v = fmaxf(v, sm->scores[i]);
        #pragma unroll
        for (int o = 16; o; o >>= 1) v = fmaxf(v, __shfl_xor_sync(0xffffffffu, v, o));
        if (tid == 0) sm->red[0] = v;
    }
    __syncthreads();
    if (tid < THALF) {
        float mx = sm->red[0];
        e0 = __expf(score0 - mx);    // masked: exp(-huge) -> 0
        e1 = __expf(score1 - mx);
        sm->scores[tid] = e0;
        sm->scores[tid + THALF] = e1;
    }
    __syncthreads();
    if (tid < 32) {
        float v = 0.0f;
        for (int i = tid; i < T_LEN; i += 32) v += sm->scores[i];
        #pragma unroll
        for (int o = 16; o; o >>= 1) v += __shfl_xor_sync(0xffffffffu, v, o);
        if (tid == 0) sm->red[1] = __fdividef(1.0f, v);
    }
    __syncthreads();
    if (tid < THALF) {
        float inv = sm->red[1];
        sm->scores[tid]          = e0 * inv * (float)m0;
        sm->scores[tid + THALF]  = e1 * inv * (float)m1;
    }
    __syncthreads();

    // ---- out[b,d] = sum_t p[t] * fact[t,d]  (two half-T partials)
    {
        int d = tid & 63, half = tid >> 6;
        float acc = 0.0f;
        int tstart = half * THALF;
        for (int tt = tstart; tt < tstart + THALF; tt++)
            acc += sm->scores[tt] * sm->fact[tt * FACT_STRIDE + d];
        sm->partial[tid] = acc;
    }
    __syncthreads();
    if (tid < D_DIM)
        out[b * D_DIM + tid] = sm->partial[tid] + sm->partial[64 + tid];
}

extern "C" void kernel_launch(void* const* d_in, const int* in_sizes, int n_in,
                              void* d_out, int out_size)
{
    const float* query = (const float*)d_in[0];
    const float* fact  = (const float*)d_in[1];
    const int*   mask  = (const int*)  d_in[2];
    const float* W1    = (const float*)d_in[3];
    const float* b1    = (const float*)d_in[4];
    const float* W2    = (const float*)d_in[5];
    const float* b2    = (const float*)d_in[6];
    const float* W3    = (const float*)d_in[7];
    const float* b3    = (const float*)d_in[8];
    float* out = (float*)d_out;

    const int B = in_sizes[0] / D_DIM;           // 4096
    const int smem_bytes = (int)sizeof(Smem);    // ~90 KB (needs opt-in)
    cudaFuncSetAttribute(din_attn_kernel,
                         cudaFuncAttributeMaxDynamicSharedMemorySize, smem_bytes);
    din_attn_kernel<<<B, TB, smem_bytes>>>(query, fact, mask, W1, b1, W2, b2,
                                           W3, b3, out);
}

// round 10
// speedup vs baseline: 1.2963x; 1.2523x over previous
#include <cuda_runtime.h>

// DIN-style attention, algebraically refactored:
//   comb@W1 = fact @ A_b + qW_b,  A_b[d,h] = W1a - W1d + q[d]*W1c (per batch)
// R9: occupancy fix. R8 measured 529us with occ=12.2%, issue=36.1% (2 CTAs/SM,
// 2 warps/SMSP -> stall-bound; fma only 43.6%). fact tile goes bf16 in smem
// (54.4KB -> 27.2KB) so smem ~62.7KB -> 3 CTAs/SM (12 warps). Epilogue re-reads
// fp32 fact from global (coalesced, L2-hot) to keep output precision. Layer-1
// uses bf16 fact (error ~1e-4 on final output, budget 1e-3). regs capped via
// launch_bounds(128,3). 2-t blocking retained (that part worked: L1 75.8->47.9).
// (R10 = R9 resubmitted verbatim; R9 bench was a broker acquisition timeout.)

typedef unsigned long long ull;

#define TB 128
#define T_LEN 200
#define THALF 100       // threads 0..99 handle t and t+100
#define D_DIM 64
#define H1 80
#define HQ 20           // h-chunk width (layer-1 partial, then drained)
#define H2 40
#define FBF_STRIDE 68   // u16 units; 136B rows -> conflict-free LDS.64 per-lane-t

struct __align__(16) Smem {
    float A[D_DIM * H1];                   // 20480 B  combined layer-1 weight
    unsigned short factbf[T_LEN * FBF_STRIDE]; // 27200 B  fact tile, bf16
    float W2s[H1 * H2];                    // 12800 B
    float qW[H1];                          // per-b layer-1 bias (b1 + q-path)
    float q[D_DIM];
    float b2s[H2];
    float W3s[H2];
    float b3s;
    float red[2];
    float scores[T_LEN];
    float partial[128];
};

static __device__ __forceinline__ ull fma2(ull a, ull b, ull c) {
    ull d;
    asm("fma.rn.f32x2 %0, %1, %2, %3;" : "=l"(d) : "l"(a), "l"(b), "l"(c));
    return d;
}
static __device__ __forceinline__ ull pack2(float x, float y) {
    ull r;
    asm("mov.b64 %0, {%1, %2};" : "=l"(r) : "f"(x), "f"(y));
    return r;
}
// duplicate a 32-bit fp32 bit-pattern into both halves of a packed f32x2
static __device__ __forceinline__ ull dup2u(unsigned x) {
    ull r;
    asm("mov.b64 %0, {%1, %1};" : "=l"(r) : "r"(x));
    return r;
}
static __device__ __forceinline__ void unpack2(ull v, float& x, float& y) {
    asm("mov.b64 {%0, %1}, %2;" : "=f"(x), "=f"(y) : "l"(v));
}
static __device__ __forceinline__ float sigm(float x) {
    return __fdividef(1.0f, 1.0f + __expf(-x));
}
// two fp32 -> packed bf16x2 (lower = a, upper = b)
static __device__ __forceinline__ unsigned bf16x2_of(float a, float b) {
    unsigned r;
    asm("cvt.rn.bf16x2.f32 %0, %1, %2;" : "=r"(r) : "f"(b), "f"(a));
    return r;
}

__global__ __launch_bounds__(TB, 3)
void din_attn_kernel(const float* __restrict__ query,
                     const float* __restrict__ fact,
                     const int*   __restrict__ mask,
                     const float* __restrict__ W1,
                     const float* __restrict__ b1,
                     const float* __restrict__ W2,
                     const float* __restrict__ b2,
                     const float* __restrict__ W3,
                     const float* __restrict__ b3,
                     float* __restrict__ out)
{
    extern __shared__ Smem smem_raw[];
    Smem* sm = smem_raw;
    const int tid = threadIdx.x;
    const int b   = blockIdx.x;

    if (tid < D_DIM) sm->q[tid] = query[b * D_DIM + tid];
    __syncthreads();

    // ---- Prologue: threads 0-47 stage fact (fp32 -> bf16); 48-127 build weights.
    if (tid < 48) {
        const float4* src = (const float4*)(fact + (size_t)b * (T_LEN * D_DIM));
        for (int i = tid; i < T_LEN * D_DIM / 4; i += 48) {
            float4 v = src[i];
            int t  = i >> 4;            // 16 float4 per row of 64
            int d4 = i & 15;
            uint2 pk;
            pk.x = bf16x2_of(v.x, v.y); // lower = d0, upper = d1
            pk.y = bf16x2_of(v.z, v.w);
            *(uint2*)&sm->factbf[t * FBF_STRIDE + d4 * 4] = pk;
        }
    } else {
        const int id = tid - 48;        // 0..79
        // A[d,h] = W1[d,h] - W1[192+d,h] + q[d]*W1[128+d,h]
        for (int i = id; i < D_DIM * H1; i += 80) {
            int d = i / H1, h = i - d * H1;
            float wa = W1[d * H1 + h];
            float wc = W1[(128 + d) * H1 + h];
            float wd = W1[(192 + d) * H1 + h];
            sm->A[i] = wa - wd + sm->q[d] * wc;
        }
        // qW[h] = b1[h] + sum_d q[d]*(W1[64+d,h] + W1[192+d,h])
        {
            float a = b1[id];
            #pragma unroll 4
            for (int d = 0; d < D_DIM; d++)
                a += sm->q[d] * (W1[(64 + d) * H1 + id] + W1[(192 + d) * H1 + id]);
            sm->qW[id] = a;
        }
        for (int i = id; i < H1 * H2; i += 80) sm->W2s[i] = W2[i];
        if (id < H2) sm->b2s[id] = b2[id];
        if (id < H2) sm->W3s[id] = W3[id];
        if (id == 79) sm->b3s = b3[0];
    }
    __syncthreads();

    float score0 = 0.0f, score1 = 0.0f;
    int   m0 = 0, m1 = 0;
    float e0 = 0.0f, e1 = 0.0f;

    if (tid < THALF) {
        const int t0 = tid, t1 = tid + THALF;
        m0 = mask[b * T_LEN + t0];
        m1 = mask[b * T_LEN + t1];
        const unsigned short* fr0 = &sm->factbf[t0 * FBF_STRIDE];
        const unsigned short* fr1 = &sm->factbf[t1 * FBF_STRIDE];

        // ---- Layer-2 accumulators persist across all 4 h-chunks (2 t's).
        ull acc2_0[H2 / 2], acc2_1[H2 / 2];
        const ull* b2p = (const ull*)sm->b2s;
        #pragma unroll
        for (int i = 0; i < H2 / 2; i++) { acc2_0[i] = b2p[i]; acc2_1[i] = b2p[i]; }

        #pragma unroll
        for (int c = 0; c < H1 / HQ; c++) {
            const int h0 = c * HQ;

            // Layer-1 partial over this 20-wide h-chunk, both t's.
            ull a1_0[HQ / 2], a1_1[HQ / 2];
            const ull* qwp = (const ull*)(sm->qW + h0);
            #pragma unroll
            for (int i = 0; i < HQ / 2; i++) { a1_0[i] = qwp[i]; a1_1[i] = qwp[i]; }

            #pragma unroll 2
            for (int d4 = 0; d4 < D_DIM / 4; d4++) {
                // 4 bf16 fact values per t: expand to fp32 bit patterns
                uint2 r0 = *(const uint2*)(fr0 + 4 * d4);
                uint2 r1 = *(const uint2*)(fr1 + 4 * d4);
                unsigned va[4], vb[4];
                va[0] = r0.x << 16; va[1] = r0.x & 0xFFFF0000u;
                va[2] = r0.y << 16; va[3] = r0.y & 0xFFFF0000u;
                vb[0] = r1.x << 16; vb[1] = r1.x & 0xFFFF0000u;
                vb[2] = r1.y << 16; vb[3] = r1.y & 0xFFFF0000u;
                #pragma unroll
                for (int dd = 0; dd < 4; dd++) {
                    ull p0 = dup2u(va[dd]);
                    ull p1 = dup2u(vb[dd]);
                    const ulonglong2* row =
                        (const ulonglong2*)(sm->A + (4 * d4 + dd) * H1 + h0);
                    #pragma unroll
                    for (int j = 0; j < HQ / 4; j++) {
                        ulonglong2 a = row[j];     // one load feeds both t's
                        a1_0[2 * j]     = fma2(p0, a.x, a1_0[2 * j]);
                        a1_0[2 * j + 1] = fma2(p0, a.y, a1_0[2 * j + 1]);
                        a1_1[2 * j]     = fma2(p1, a.x, a1_1[2 * j]);
                        a1_1[2 * j + 1] = fma2(p1, a.y, a1_1[2 * j + 1]);
                    }
                }
            }

            // Sigmoid + drain chunk into layer-2 accumulators (both t's).
            #pragma unroll
            for (int i = 0; i < HQ / 2; i++) {
                float x0, y0, x1, y1;
                unpack2(a1_0[i], x0, y0);
                unpack2(a1_1[i], x1, y1);
                ull g00 = pack2(sigm(x0), sigm(x0));   // t0, h even
                ull g01 = pack2(sigm(y0), sigm(y0));   // t0, h odd
                ull g10 = pack2(sigm(x1), sigm(x1));   // t1, h even
                ull g11 = pack2(sigm(y1), sigm(y1));   // t1, h odd
                const ulonglong2* r0 =
                    (const ulonglong2*)(sm->W2s + (h0 + 2 * i) * H2);
                const ulonglong2* r1 =
                    (const ulonglong2*)(sm->W2s + (h0 + 2 * i + 1) * H2);
                #pragma unroll
                for (int j = 0; j < H2 / 4; j++) {
                    ulonglong2 w0 = r0[j];
                    ulonglong2 w1 = r1[j];
                    acc2_0[2 * j]     = fma2(g00, w0.x, acc2_0[2 * j]);
                    acc2_0[2 * j + 1] = fma2(g00, w0.y, acc2_0[2 * j + 1]);
                    acc2_0[2 * j]     = fma2(g01, w1.x, acc2_0[2 * j]);
                    acc2_0[2 * j + 1] = fma2(g01, w1.y, acc2_0[2 * j + 1]);
                    acc2_1[2 * j]     = fma2(g10, w0.x, acc2_1[2 * j]);
                    acc2_1[2 * j + 1] = fma2(g10, w0.y, acc2_1[2 * j + 1]);
                    acc2_1[2 * j]     = fma2(g11, w1.x, acc2_1[2 * j]);
                    acc2_1[2 * j + 1] = fma2(g11, w1.y, acc2_1[2 * j + 1]);
                }
            }
        }

        // ---- Layer 3: score = sigmoid(h2) @ W3 + b3 (both t's)
        ull sp0 = 0ull, sp1 = 0ull;
        const ull* W3p = (const ull*)sm->W3s;
        #pragma unroll
        for (int i = 0; i < H2 / 2; i++) {
            float x0, y0, x1, y1;
            unpack2(acc2_0[i], x0, y0);
            unpack2(acc2_1[i], x1, y1);
            ull w = W3p[i];
            sp0 = fma2(pack2(sigm(x0), sigm(y0)), w, sp0);
            sp1 = fma2(pack2(sigm(x1), sigm(y1)), w, sp1);
        }
        float sx, sy;
        unpack2(sp0, sx, sy);
        score0 = sx + sy + sm->b3s;
        unpack2(sp1, sx, sy);
        score1 = sx + sy + sm->b3s;
        if (m0 != 1) score0 = -2147483648.0f;   // NEG_BIG = -2^31 exactly
        if (m1 != 1) score1 = -2147483648.0f;
        sm->scores[t0] = score0;
        sm->scores[t1] = score1;
    }
    __syncthreads();

    // ---- Masked softmax over T (block reductions by warp 0)
    if (tid < 32) {
        float v = -3.4e38f;
        for (int i = tid; i < T_LEN; i += 32) v = fmaxf(v, sm->scores[i]);
        #pragma unroll
        for (int o = 16; o; o >>= 1) v = fmaxf(v, __shfl_xor_sync(0xffffffffu, v, o));
        if (tid == 0) sm->red[0] = v;
    }
    __syncthreads();
    if (tid < THALF) {
        float mx = sm->red[0];
        e0 = __expf(score0 - mx);    // masked: exp(-huge) -> 0
        e1 = __expf(score1 - mx);
        sm->scores[tid] = e0;
        sm->scores[tid + THALF] = e1;
    }
    __syncthreads();
    if (tid < 32) {
        float v = 0.0f;
        for (int i = tid; i < T_LEN; i += 32) v += sm->scores[i];
        #pragma unroll
        for (int o = 16; o; o >>= 1) v += __shfl_xor_sync(0xffffffffu, v, o);
        if (tid == 0) sm->red[1] = __fdividef(1.0f, v);
    }
    __syncthreads();
    if (tid < THALF) {
        float inv = sm->red[1];
        sm->scores[tid]          = e0 * inv * (float)m0;
        sm->scores[tid + THALF]  = e1 * inv * (float)m1;
    }
    __syncthreads();

    // ---- out[b,d] = sum_t p[t] * fact[t,d] — fp32 fact re-read from GMEM
    // (coalesced: lanes span consecutive d; lines are L2-hot from prologue)
    {
        int d = tid & 63, half = tid >> 6;
        const float* fsrc = fact + (size_t)b * (T_LEN * D_DIM) + d;
        float acc = 0.0f;
        int tstart = half * THALF;
        #pragma unroll 4
        for (int tt = tstart; tt < tstart + THALF; tt++)
            acc += sm->scores[tt] * fsrc[(size_t)tt * D_DIM];
        sm->partial[tid] = acc;
    }
    __syncthreads();
    if (tid < D_DIM)
        out[b * D_DIM + tid] = sm->partial[tid] + sm->partial[64 + tid];
}

extern "C" void kernel_launch(void* const* d_in, const int* in_sizes, int n_in,
                              void* d_out, int out_size)
{
    const float* query = (const float*)d_in[0];
    const float* fact  = (const float*)d_in[1];
    const int*   mask  = (const int*)  d_in[2];
    const float* W1    = (const float*)d_in[3];
    const float* b1    = (const float*)d_in[4];
    const float* W2    = (const float*)d_in[5];
    const float* b2    = (const float*)d_in[6];
    const float* W3    = (const float*)d_in[7];
    const float* b3    = (const float*)d_in[8];
    float* out = (float*)d_out;

    const int B = in_sizes[0] / D_DIM;           // 4096
    const int smem_bytes = (int)sizeof(Smem);    // ~62.7 KB (needs opt-in)
    cudaFuncSetAttribute(din_attn_kernel,
                         cudaFuncAttributeMaxDynamicSharedMemorySize, smem_bytes);
    din_attn_kernel<<<B, TB, smem_bytes>>>(query, fact, mask, W1, b1, W2, b2,
                                           W3, b3, out);
}

// round 13
// speedup vs baseline: 1.7794x; 1.3727x over previous
#include <cuda_runtime.h>
#include <cuda_bf16.h>
#include <cstdint>

// DIN attention. R12: layer-1 (fact@Aw^T) on tensor cores via warp-level
// mma.sync.m16n8k16 bf16 (base-target PTX; tcgen05 is 'a'-gated and the
// harness compiles PTX at sm_103, so R11's TMEM path cannot compile).
//   D[t,h] = fact[t,d] @ Aw[h,d]^T : 13 m-tiles x 10 n-tiles x 4 k-steps.
// Epilogue per tile: +qW, sigmoid, bf16 G into smem (reusing the fact tile,
// which is dead once all warps hold their A fragments). Layer-2/3 scalar
// FFMA2 with the measured-good 2-t shared-W2 drain (R10). 3 CTAs/SM kept.
// (R13 = R12 resubmitted verbatim; R12 bench was a broker acquisition timeout.)

typedef unsigned long long ull;

#define TB 128
#define T_LEN 200
#define THALF 100
#define D_DIM 64
#define H1 80
#define H2 40
#define FST 72      // fact tile stride, u16 (36 words = 4 mod 32: frag-load conflict-free)
#define GST 82      // G stride, u16 (41 words, odd: layer-2 reads conflict-free)
#define PST 88      // P stride, u32 (24 mod 32: B-frag loads conflict-free)

struct __align__(16) Smem {
    unsigned short fg[16400];   // 32800B union: fact bf16 [208][72] / G bf16 [200][82]
    unsigned Pw[32 * PST];      // 11264B packed AwT: P[d/2][h] = (Aw[h,d], Aw[h,d+1])
    float W2s[H1 * H2];         // 12800B
    float qW[H1];
    float q[D_DIM];
    float b2s[H2];
    float W3s[H2];
    float b3s;
    float red[2];
    float scores[T_LEN];
    float partial[128];
};

static __device__ __forceinline__ ull fma2(ull a, ull b, ull c) {
    ull d;
    asm("fma.rn.f32x2 %0, %1, %2, %3;" : "=l"(d) : "l"(a), "l"(b), "l"(c));
    return d;
}
static __device__ __forceinline__ ull pack2(float x, float y) {
    ull r; asm("mov.b64 %0, {%1, %2};" : "=l"(r) : "f"(x), "f"(y)); return r;
}
static __device__ __forceinline__ ull dup2u(unsigned x) {
    ull r; asm("mov.b64 %0, {%1, %1};" : "=l"(r) : "r"(x)); return r;
}
static __device__ __forceinline__ void unpack2(ull v, float& x, float& y) {
    asm("mov.b64 {%0, %1}, %2;" : "=f"(x), "=f"(y) : "l"(v));
}
static __device__ __forceinline__ float sigm(float x) {
    return __fdividef(1.0f, 1.0f + __expf(-x));
}
// packed bf16x2: lower = a, upper = b
static __device__ __forceinline__ unsigned bf16x2_of(float a, float b) {
    unsigned r;
    asm("cvt.rn.bf16x2.f32 %0, %1, %2;" : "=r"(r) : "f"(b), "f"(a));
    return r;
}
// D += A@B, m16n8k16 bf16 -> f32
static __device__ __forceinline__ void mma16816(
    float& c0, float& c1, float& c2, float& c3,
    unsigned a0, unsigned a1, unsigned a2, unsigned a3,
    unsigned b0, unsigned b1)
{
    asm volatile(
        "mma.sync.aligned.m16n8k16.row.col.f32.bf16.bf16.f32 "
        "{%0,%1,%2,%3}, {%4,%5,%6,%7}, {%8,%9}, {%0,%1,%2,%3};"
        : "+f"(c0), "+f"(c1), "+f"(c2), "+f"(c3)
        : "r"(a0), "r"(a1), "r"(a2), "r"(a3), "r"(b0), "r"(b1));
}

__global__ __launch_bounds__(TB, 3)
void din_attn_kernel(const float* __restrict__ query,
                     const float* __restrict__ fact,
                     const int*   __restrict__ mask,
                     const float* __restrict__ W1,
                     const float* __restrict__ b1,
                     const float* __restrict__ W2,
                     const float* __restrict__ b2,
                     const float* __restrict__ W3,
                     const float* __restrict__ b3,
                     float* __restrict__ out)
{
    extern __shared__ char smem_raw[];
    Smem* sm = (Smem*)smem_raw;
    const int tid  = threadIdx.x;
    const int wid  = tid >> 5;
    const int lane = tid & 31;
    const int gid  = lane >> 2;     // fragment group id (row group)
    const int ctid = lane & 3;      // thread-in-group (col pair)
    const int b    = blockIdx.x;

    if (tid < D_DIM) sm->q[tid] = query[b * D_DIM + tid];
    __syncthreads();

    // ---- Prologue ----
    {   // fact -> bf16 tile [t][d], stride FST
        const float4* src = (const float4*)(fact + (size_t)b * (T_LEN * D_DIM));
        for (int i = tid; i < T_LEN * D_DIM / 4; i += TB) {
            float4 v = src[i];
            int t = i >> 4, d4 = i & 15;
            uint2 pk;
            pk.x = bf16x2_of(v.x, v.y);
            pk.y = bf16x2_of(v.z, v.w);
            *(uint2*)(sm->fg + t * FST + d4 * 4) = pk;
        }
        // zero pad rows 200..207 (read by last m-tile's A fragments)
        for (int i = tid; i < 8 * FST / 2; i += TB)
            ((unsigned*)(sm->fg + 200 * FST))[i] = 0;
        // P[d2][h] = bf16x2(Aw[h,2d2], Aw[h,2d2+1]);  Aw[h,d] = W1a - W1d + q[d]*W1c
        for (int i = tid; i < 32 * H1; i += TB) {
            int d2 = i / H1, h = i - d2 * H1, d = 2 * d2;
            float a0 = W1[d * H1 + h] - W1[(192 + d) * H1 + h]
                       + sm->q[d] * W1[(128 + d) * H1 + h];
            float a1 = W1[(d + 1) * H1 + h] - W1[(193 + d) * H1 + h]
                       + sm->q[d + 1] * W1[(129 + d) * H1 + h];
            sm->Pw[d2 * PST + h] = bf16x2_of(a0, a1);
        }
        if (tid < H1) {
            float a = b1[tid];
            #pragma unroll 4
            for (int d = 0; d < D_DIM; d++)
                a += sm->q[d] * (W1[(64 + d) * H1 + tid] + W1[(192 + d) * H1 + tid]);
            sm->qW[tid] = a;
        }
        for (int i = tid; i < H1 * H2; i += TB) sm->W2s[i] = W2[i];
        if (tid < H2) sm->b2s[tid] = b2[tid];
        if (tid < H2) sm->W3s[tid] = W3[tid];
        if (tid == 0) sm->b3s = b3[0];
    }
    __syncthreads();

    // ---- Layer 1 on tensor cores. Warp w owns m-tiles {w, w+4, w+8, w+12<13}.
    {
        unsigned afr[4][16];        // [mi][ks*4+r], compile-time indexed
        #pragma unroll
        for (int mi = 0; mi < 4; mi++) {
            int mt = wid + 4 * mi;
            if (mt < 13) {
                const unsigned short* base = sm->fg + (mt * 16 + gid) * FST;
                #pragma unroll
                for (int ks = 0; ks < 4; ks++) {
                    afr[mi][ks * 4 + 0] = *(const unsigned*)(base + ks * 16 + ctid * 2);
                    afr[mi][ks * 4 + 1] = *(const unsigned*)(base + 8 * FST + ks * 16 + ctid * 2);
                    afr[mi][ks * 4 + 2] = *(const unsigned*)(base + ks * 16 + 8 + ctid * 2);
                    afr[mi][ks * 4 + 3] = *(const unsigned*)(base + 8 * FST + ks * 16 + 8 + ctid * 2);
                }
            }
        }
        __syncthreads();            // all A frags in regs -> fact region dead, G may overwrite

        for (int n = 0; n < 10; n++) {
            unsigned bfr[4][2];
            #pragma unroll
            for (int ks = 0; ks < 4; ks++) {
                bfr[ks][0] = sm->Pw[(ks * 8 + ctid) * PST + n * 8 + gid];
                bfr[ks][1] = sm->Pw[(ks * 8 + 4 + ctid) * PST + n * 8 + gid];
            }
            const int h0 = n * 8 + ctid * 2;
            float2 qw = *(const float2*)(sm->qW + h0);
            #pragma unroll
            for (int mi = 0; mi < 4; mi++) {
                int mt = wid + 4 * mi;
                if (mt < 13) {
                    float c0 = 0.f, c1 = 0.f, c2 = 0.f, c3 = 0.f;
                    #pragma unroll
                    for (int ks = 0; ks < 4; ks++)
                        mma16816(c0, c1, c2, c3,
                                 afr[mi][ks * 4 + 0], afr[mi][ks * 4 + 1],
                                 afr[mi][ks * 4 + 2], afr[mi][ks * 4 + 3],
                                 bfr[ks][0], bfr[ks][1]);
                    int t0 = mt * 16 + gid, t1 = t0 + 8;
                    *(unsigned*)(sm->fg + t0 * GST + h0) =
                        bf16x2_of(sigm(c0 + qw.x), sigm(c1 + qw.y));
                    if (t1 < T_LEN)
                        *(unsigned*)(sm->fg + t1 * GST + h0) =
                            bf16x2_of(sigm(c2 + qw.x), sigm(c3 + qw.y));
                }
            }
        }
    }
    __syncthreads();

    // ---- Layer 2+3 scalar, 2-t shared-W2 drain (t, t+100) ----
    float score0 = 0.0f, score1 = 0.0f;
    int   m0 = 0, m1 = 0;
    float e0 = 0.0f, e1 = 0.0f;

    if (tid < THALF) {
        const int t0 = tid, t1 = tid + THALF;
        m0 = mask[b * T_LEN + t0];
        m1 = mask[b * T_LEN + t1];
        const unsigned* g0p = (const unsigned*)(sm->fg + t0 * GST);
        const unsigned* g1p = (const unsigned*)(sm->fg + t1 * GST);

        ull acc2_0[H2 / 2], acc2_1[H2 / 2];
        const ull* b2p = (const ull*)sm->b2s;
        #pragma unroll
        for (int i = 0; i < H2 / 2; i++) { acc2_0[i] = b2p[i]; acc2_1[i] = b2p[i]; }

        #pragma unroll 2
        for (int hp = 0; hp < H1 / 2; hp++) {     // h = 2hp, 2hp+1
            unsigned ga = g0p[hp], gb = g1p[hp];
            ull g00 = dup2u(ga << 16), g01 = dup2u(ga & 0xFFFF0000u);
            ull g10 = dup2u(gb << 16), g11 = dup2u(gb & 0xFFFF0000u);
            const ulonglong2* r0 = (const ulonglong2*)(sm->W2s + (2 * hp) * H2);
            const ulonglong2* r1 = (const ulonglong2*)(sm->W2s + (2 * hp + 1) * H2);
            #pragma unroll
            for (int j = 0; j < H2 / 4; j++) {
                ulonglong2 w0 = r0[j], w1 = r1[j];
                acc2_0[2 * j]     = fma2(g00, w0.x, acc2_0[2 * j]);
                acc2_0[2 * j + 1] = fma2(g00, w0.y, acc2_0[2 * j + 1]);
                acc2_0[2 * j]     = fma2(g01, w1.x, acc2_0[2 * j]);
                acc2_0[2 * j + 1] = fma2(g01, w1.y, acc2_0[2 * j + 1]);
                acc2_1[2 * j]     = fma2(g10, w0.x, acc2_1[2 * j]);
                acc2_1[2 * j + 1] = fma2(g10, w0.y, acc2_1[2 * j + 1]);
                acc2_1[2 * j]     = fma2(g11, w1.x, acc2_1[2 * j]);
                acc2_1[2 * j + 1] = fma2(g11, w1.y, acc2_1[2 * j + 1]);
            }
        }

        ull sp0 = 0ull, sp1 = 0ull;
        const ull* W3p = (const ull*)sm->W3s;
        #pragma unroll
        for (int i = 0; i < H2 / 2; i++) {
            float x0, y0, x1, y1;
            unpack2(acc2_0[i], x0, y0);
            unpack2(acc2_1[i], x1, y1);
            ull w = W3p[i];
            sp0 = fma2(pack2(sigm(x0), sigm(y0)), w, sp0);
            sp1 = fma2(pack2(sigm(x1), sigm(y1)), w, sp1);
        }
        float sx, sy;
        unpack2(sp0, sx, sy); score0 = sx + sy + sm->b3s;
        unpack2(sp1, sx, sy); score1 = sx + sy + sm->b3s;
        if (m0 != 1) score0 = -2147483648.0f;   // NEG_BIG = -2^31
        if (m1 != 1) score1 = -2147483648.0f;
        sm->scores[t0] = score0;
        sm->scores[t1] = score1;
    }
    __syncthreads();

    // ---- Masked softmax over T ----
    if (tid < 32) {
        float v = -3.4e38f;
        for (int i = tid; i < T_LEN; i += 32) v = fmaxf(v, sm->scores[i]);
        #pragma unroll
        for (int o = 16; o; o >>= 1) v = fmaxf(v, __shfl_xor_sync(0xffffffffu, v, o));
        if (tid == 0) sm->red[0] = v;
    }
    __syncthreads();
    if (tid < THALF) {
        float mx = sm->red[0];
        e0 = __expf(score0 - mx);
        e1 = __expf(score1 - mx);
        sm->scores[tid] = e0;
        sm->scores[tid + THALF] = e1;
    }
    __syncthreads();
    if (tid < 32) {
        float v = 0.0f;
        for (int i = tid; i < T_LEN; i += 32) v += sm->scores[i];
        #pragma unroll
        for (int o = 16; o; o >>= 1) v += __shfl_xor_sync(0xffffffffu, v, o);
        if (tid == 0) sm->red[1] = __fdividef(1.0f, v);
    }
    __syncthreads();
    if (tid < THALF) {
        float inv = sm->red[1];
        sm->scores[tid]         = e0 * inv * (float)m0;
        sm->scores[tid + THALF] = e1 * inv * (float)m1;
    }
    __syncthreads();

    // ---- out[b,d] = sum_t p[t] * fact[t,d]  (fp32 fact from GMEM, coalesced)
    {
        int d = tid & 63, half = tid >> 6;
        const float* fsrc = fact + (size_t)b * (T_LEN * D_DIM) + d;
        float acc = 0.0f;
        int tstart = half * THALF;
        #pragma unroll 4
        for (int tt = tstart; tt < tstart + THALF; tt++)
            acc += sm->scores[tt] * fsrc[(size_t)tt * D_DIM];
        sm->partial[tid] = acc;
    }
    __syncthreads();
    if (tid < D_DIM)
        out[b * D_DIM + tid] = sm->partial[tid] + sm->partial[64 + tid];
}

extern "C" void kernel_launch(void* const* d_in, const int* in_sizes, int n_in,
                              void* d_out, int out_size)
{
    const float* query = (const float*)d_in[0];
    const float* fact  = (const float*)d_in[1];
    const int*   mask  = (const int*)  d_in[2];
    const float* W1    = (const float*)d_in[3];
    const float* b1    = (const float*)d_in[4];
    const float* W2    = (const float*)d_in[5];
    const float* b2    = (const float*)d_in[6];
    const float* W3    = (const float*)d_in[7];
    const float* b3    = (const float*)d_in[8];
    float* out = (float*)d_out;

    const int B = in_sizes[0] / D_DIM;           // 4096
    const int smem_bytes = (int)sizeof(Smem);    // ~59 KB
    cudaFuncSetAttribute(din_attn_kernel,
                         cudaFuncAttributeMaxDynamicSharedMemorySize, smem_bytes);
    din_attn_kernel<<<B, TB, smem_bytes>>>(query, fact, mask, W1, b1, W2, b2,
                                           W3, b3, out);
}

// round 14
// speedup vs baseline: 2.2205x; 1.2479x over previous
#include <cuda_runtime.h>
#include <cuda_bf16.h>
#include <cstdint>

// DIN attention. R14: BOTH big layers on tensor cores (m16n8k16 bf16).
//   GEMM1: D1[t,h] = fact[t,d] @ Aw[h,d]^T   (13 mt x 10 nt x 4 ks)
//   GEMM2: D2[t,k] = G[t,h]   @ W2[h,k]      (13 mt x  5 nt x 5 ks)
// GEMM1 epilogue: +qW, sigmoid -> G bf16 (reuses fact smem). GEMM2 epilogue
// fuses layer-3: sigmoid(D2+b2) dot W3, shfl-reduced across the 4-lane ctid
// group -> scores. Softmax + fp32-gmem weighted-sum epilogue unchanged.
// R13 measured 307.7us with layer-2 scalar (3200 fma2/thread) -- now deleted.

typedef unsigned long long ull;

#define TB 128
#define T_LEN 200
#define THALF 100
#define D_DIM 64
#define H1 80
#define H2 40
#define FST 72      // fact stride u16 (36 w = 4 mod 32: GEMM1 A-frag conflict-free)
#define GST 88      // G stride u16 (44 w = 12 mod 32: GEMM2 A-frag + G-store conflict-free)
#define PST 88      // Pw stride u32 (24 mod 32: B-frag conflict-free)
#define P2ST 56     // P2 stride u32 (24 mod 32: B-frag conflict-free)

struct __align__(16) Smem {
    unsigned short fg[208 * GST];   // 36608B union: fact bf16 [208][72] / G bf16 [208][88]
    unsigned Pw[32 * PST];          // 11264B packed AwT: Pw[d/2][h]
    unsigned P2[40 * P2ST];         // 8960B  packed W2:  P2[h/2][k]
    float qW[H1];
    float q[D_DIM];
    float b2s[H2];
    float W3s[H2];
    float b3s;
    float red[2];
    float scores[T_LEN];
    float partial[128];
};

static __device__ __forceinline__ float sigm(float x) {
    return __fdividef(1.0f, 1.0f + __expf(-x));
}
// packed bf16x2: lower = a, upper = b
static __device__ __forceinline__ unsigned bf16x2_of(float a, float b) {
    unsigned r;
    asm("cvt.rn.bf16x2.f32 %0, %1, %2;" : "=r"(r) : "f"(b), "f"(a));
    return r;
}
// D += A@B, m16n8k16 bf16 -> f32
static __device__ __forceinline__ void mma16816(
    float& c0, float& c1, float& c2, float& c3,
    unsigned a0, unsigned a1, unsigned a2, unsigned a3,
    unsigned b0, unsigned b1)
{
    asm volatile(
        "mma.sync.aligned.m16n8k16.row.col.f32.bf16.bf16.f32 "
        "{%0,%1,%2,%3}, {%4,%5,%6,%7}, {%8,%9}, {%0,%1,%2,%3};"
        : "+f"(c0), "+f"(c1), "+f"(c2), "+f"(c3)
        : "r"(a0), "r"(a1), "r"(a2), "r"(a3), "r"(b0), "r"(b1));
}

__global__ __launch_bounds__(TB, 3)
void din_attn_kernel(const float* __restrict__ query,
                     const float* __restrict__ fact,
                     const int*   __restrict__ mask,
                     const float* __restrict__ W1,
                     const float* __restrict__ b1,
                     const float* __restrict__ W2,
                     const float* __restrict__ b2,
                     const float* __restrict__ W3,
                     const float* __restrict__ b3,
                     float* __restrict__ out)
{
    extern __shared__ char smem_raw[];
    Smem* sm = (Smem*)smem_raw;
    const int tid  = threadIdx.x;
    const int wid  = tid >> 5;
    const int lane = tid & 31;
    const int gid  = lane >> 2;     // fragment row group
    const int ctid = lane & 3;      // thread-in-group
    const int b    = blockIdx.x;

    if (tid < D_DIM) sm->q[tid] = query[b * D_DIM + tid];
    __syncthreads();

    // ---- Prologue ----
    {   // fact -> bf16 tile [t][d], stride FST
        const float4* src = (const float4*)(fact + (size_t)b * (T_LEN * D_DIM));
        for (int i = tid; i < T_LEN * D_DIM / 4; i += TB) {
            float4 v = src[i];
            int t = i >> 4, d4 = i & 15;
            uint2 pk;
            pk.x = bf16x2_of(v.x, v.y);
            pk.y = bf16x2_of(v.z, v.w);
            *(uint2*)(sm->fg + t * FST + d4 * 4) = pk;
        }
        // zero fact pad rows 200..207
        for (int i = tid; i < 8 * FST / 2; i += TB)
            ((unsigned*)(sm->fg + 200 * FST))[i] = 0;
        // Pw[d2][h] = bf16x2(Aw[h,2d2], Aw[h,2d2+1]);  Aw[h,d] = W1a - W1d + q[d]*W1c
        for (int i = tid; i < 32 * H1; i += TB) {
            int d2 = i / H1, h = i - d2 * H1, d = 2 * d2;
            float a0 = W1[d * H1 + h] - W1[(192 + d) * H1 + h]
                       + sm->q[d] * W1[(128 + d) * H1 + h];
            float a1 = W1[(d + 1) * H1 + h] - W1[(193 + d) * H1 + h]
                       + sm->q[d + 1] * W1[(129 + d) * H1 + h];
            sm->Pw[d2 * PST + h] = bf16x2_of(a0, a1);
        }
        // P2[h2][k] = bf16x2(W2[2h2][k], W2[2h2+1][k])
        for (int i = tid; i < 40 * H2; i += TB) {
            int h2 = i / H2, k = i - h2 * H2;
            sm->P2[h2 * P2ST + k] =
                bf16x2_of(W2[(2 * h2) * H2 + k], W2[(2 * h2 + 1) * H2 + k]);
        }
        if (tid < H1) {
            float a = b1[tid];
            #pragma unroll 4
            for (int d = 0; d < D_DIM; d++)
                a += sm->q[d] * (W1[(64 + d) * H1 + tid] + W1[(192 + d) * H1 + tid]);
            sm->qW[tid] = a;
        }
        if (tid < H2) sm->b2s[tid] = b2[tid];
        if (tid < H2) sm->W3s[tid] = W3[tid];
        if (tid == 0) sm->b3s = b3[0];
    }
    __syncthreads();

    // ---- GEMM1 on tensor cores. Warp w owns m-tiles {w, w+4, w+8, w+12<13}.
    {
        unsigned afr[4][16];
        #pragma unroll
        for (int mi = 0; mi < 4; mi++) {
            int mt = wid + 4 * mi;
            if (mt < 13) {
                const unsigned short* base = sm->fg + (mt * 16 + gid) * FST;
                #pragma unroll
                for (int ks = 0; ks < 4; ks++) {
                    afr[mi][ks * 4 + 0] = *(const unsigned*)(base + ks * 16 + ctid * 2);
                    afr[mi][ks * 4 + 1] = *(const unsigned*)(base + 8 * FST + ks * 16 + ctid * 2);
                    afr[mi][ks * 4 + 2] = *(const unsigned*)(base + ks * 16 + 8 + ctid * 2);
                    afr[mi][ks * 4 + 3] = *(const unsigned*)(base + 8 * FST + ks * 16 + 8 + ctid * 2);
                }
            }
        }
        __syncthreads();            // A frags in regs -> fact region dead, G may overwrite

        for (int n = 0; n < 10; n++) {
            unsigned bfr[4][2];
            #pragma unroll
            for (int ks = 0; ks < 4; ks++) {
                bfr[ks][0] = sm->Pw[(ks * 8 + ctid) * PST + n * 8 + gid];
                bfr[ks][1] = sm->Pw[(ks * 8 + 4 + ctid) * PST + n * 8 + gid];
            }
            const int h0 = n * 8 + ctid * 2;
            float2 qw = *(const float2*)(sm->qW + h0);
            #pragma unroll
            for (int mi = 0; mi < 4; mi++) {
                int mt = wid + 4 * mi;
                if (mt < 13) {
                    float c0 = 0.f, c1 = 0.f, c2 = 0.f, c3 = 0.f;
                    #pragma unroll
                    for (int ks = 0; ks < 4; ks++)
                        mma16816(c0, c1, c2, c3,
                                 afr[mi][ks * 4 + 0], afr[mi][ks * 4 + 1],
                                 afr[mi][ks * 4 + 2], afr[mi][ks * 4 + 3],
                                 bfr[ks][0], bfr[ks][1]);
                    int t0 = mt * 16 + gid, t1 = t0 + 8;
                    *(unsigned*)(sm->fg + t0 * GST + h0) =
                        bf16x2_of(sigm(c0 + qw.x), sigm(c1 + qw.y));
                    if (t1 < T_LEN)
                        *(unsigned*)(sm->fg + t1 * GST + h0) =
                            bf16x2_of(sigm(c2 + qw.x), sigm(c3 + qw.y));
                }
            }
        }
        // zero G pad rows 200..207 (read by GEMM2's last m-tile)
        for (int i = tid; i < 8 * GST / 2; i += TB)
            ((unsigned*)(sm->fg + 200 * GST))[i] = 0;
    }
    __syncthreads();

    // ---- GEMM2 + fused layer-3 ----
    {
        unsigned a2[4][20];         // [mi][ks*4+r], K=80 -> 5 k-steps
        #pragma unroll
        for (int mi = 0; mi < 4; mi++) {
            int mt = wid + 4 * mi;
            if (mt < 13) {
                const unsigned short* base = sm->fg + (mt * 16 + gid) * GST;
                #pragma unroll
                for (int ks = 0; ks < 5; ks++) {
                    a2[mi][ks * 4 + 0] = *(const unsigned*)(base + ks * 16 + ctid * 2);
                    a2[mi][ks * 4 + 1] = *(const unsigned*)(base + 8 * GST + ks * 16 + ctid * 2);
                    a2[mi][ks * 4 + 2] = *(const unsigned*)(base + ks * 16 + 8 + ctid * 2);
                    a2[mi][ks * 4 + 3] = *(const unsigned*)(base + 8 * GST + ks * 16 + 8 + ctid * 2);
                }
            }
        }

        float s0[4] = {0.f, 0.f, 0.f, 0.f};   // score partials, row t0 per mi
        float s1[4] = {0.f, 0.f, 0.f, 0.f};   // row t1 per mi

        for (int n = 0; n < 5; n++) {
            unsigned bfr[5][2];
            #pragma unroll
            for (int ks = 0; ks < 5; ks++) {
                bfr[ks][0] = sm->P2[(ks * 8 + ctid) * P2ST + n * 8 + gid];
                bfr[ks][1] = sm->P2[(ks * 8 + 4 + ctid) * P2ST + n * 8 + gid];
            }
            const int k0 = n * 8 + ctid * 2;
            float2 bb = *(const float2*)(sm->b2s + k0);
            float2 w3 = *(const float2*)(sm->W3s + k0);
            #pragma unroll
            for (int mi = 0; mi < 4; mi++) {
                int mt = wid + 4 * mi;
                if (mt < 13) {
                    float c0 = 0.f, c1 = 0.f, c2 = 0.f, c3 = 0.f;
                    #pragma unroll
                    for (int ks = 0; ks < 5; ks++)
                        mma16816(c0, c1, c2, c3,
                                 a2[mi][ks * 4 + 0], a2[mi][ks * 4 + 1],
                                 a2[mi][ks * 4 + 2], a2[mi][ks * 4 + 3],
                                 bfr[ks][0], bfr[ks][1]);
                    s0[mi] += sigm(c0 + bb.x) * w3.x + sigm(c1 + bb.y) * w3.y;
                    s1[mi] += sigm(c2 + bb.x) * w3.x + sigm(c3 + bb.y) * w3.y;
                }
            }
        }

        // reduce across the 4-lane ctid group (lane = 4*gid + ctid)
        float b3v = sm->b3s;
        #pragma unroll
        for (int mi = 0; mi < 4; mi++) {
            int mt = wid + 4 * mi;
            if (mt < 13) {
                float r0 = s0[mi], r1 = s1[mi];
                r0 += __shfl_xor_sync(0xffffffffu, r0, 1);
                r0 += __shfl_xor_sync(0xffffffffu, r0, 2);
                r1 += __shfl_xor_sync(0xffffffffu, r1, 1);
                r1 += __shfl_xor_sync(0xffffffffu, r1, 2);
                int t0 = mt * 16 + gid, t1 = t0 + 8;
                if (ctid == 0) {
                    sm->scores[t0] = r0 + b3v;
                    if (t1 < T_LEN) sm->scores[t1] = r1 + b3v;
                }
            }
        }
    }
    __syncthreads();

    // ---- Mask + softmax over T ----
    float score0 = 0.0f, score1 = 0.0f;
    int   m0 = 0, m1 = 0;
    float e0 = 0.0f, e1 = 0.0f;
    if (tid < THALF) {
        m0 = mask[b * T_LEN + tid];
        m1 = mask[b * T_LEN + tid + THALF];
        score0 = (m0 == 1) ? sm->scores[tid] : -2147483648.0f;       // NEG_BIG
        score1 = (m1 == 1) ? sm->scores[tid + THALF] : -2147483648.0f;
    }
    __syncthreads();
    if (tid < THALF) {
        sm->scores[tid] = score0;
        sm->scores[tid + THALF] = score1;
    }
    __syncthreads();
    if (tid < 32) {
        float v = -3.4e38f;
        for (int i = tid; i < T_LEN; i += 32) v = fmaxf(v, sm->scores[i]);
        #pragma unroll
        for (int o = 16; o; o >>= 1) v = fmaxf(v, __shfl_xor_sync(0xffffffffu, v, o));
        if (tid == 0) sm->red[0] = v;
    }
    __syncthreads();
    if (tid < THALF) {
        float mx = sm->red[0];
        e0 = __expf(score0 - mx);
        e1 = __expf(score1 - mx);
        sm->scores[tid] = e0;
        sm->scores[tid + THALF] = e1;
    }
    __syncthreads();
    if (tid < 32) {
        float v = 0.0f;
        for (int i = tid; i < T_LEN; i += 32) v += sm->scores[i];
        #pragma unroll
        for (int o = 16; o; o >>= 1) v += __shfl_xor_sync(0xffffffffu, v, o);
        if (tid == 0) sm->red[1] = __fdividef(1.0f, v);
    }
    __syncthreads();
    if (tid < THALF) {
        float inv = sm->red[1];
        sm->scores[tid]         = e0 * inv * (float)m0;
        sm->scores[tid + THALF] = e1 * inv * (float)m1;
    }
    __syncthreads();

    // ---- out[b,d] = sum_t p[t] * fact[t,d]  (fp32 fact from GMEM, coalesced)
    {
        int d = tid & 63, half = tid >> 6;
        const float* fsrc = fact + (size_t)b * (T_LEN * D_DIM) + d;
        float acc = 0.0f;
        int tstart = half * THALF;
        #pragma unroll 4
        for (int tt = tstart; tt < tstart + THALF; tt++)
            acc += sm->scores[tt] * fsrc[(size_t)tt * D_DIM];
        sm->partial[tid] = acc;
    }
    __syncthreads();
    if (tid < D_DIM)
        out[b * D_DIM + tid] = sm->partial[tid] + sm->partial[64 + tid];
}

extern "C" void kernel_launch(void* const* d_in, const int* in_sizes, int n_in,
                              void* d_out, int out_size)
{
    const float* query = (const float*)d_in[0];
    const float* fact  = (const float*)d_in[1];
    const int*   mask  = (const int*)  d_in[2];
    const float* W1    = (const float*)d_in[3];
    const float* b1    = (const float*)d_in[4];
    const float* W2    = (const float*)d_in[5];
    const float* b2    = (const float*)d_in[6];
    const float* W3    = (const float*)d_in[7];
    const float* b3    = (const float*)d_in[8];
    float* out = (float*)d_out;

    const int B = in_sizes[0] / D_DIM;           // 4096
    const int smem_bytes = (int)sizeof(Smem);    // ~57.7 KB
    cudaFuncSetAttribute(din_attn_kernel,
                         cudaFuncAttributeMaxDynamicSharedMemorySize, smem_bytes);
    din_attn_kernel<<<B, TB, smem_bytes>>>(query, fact, mask, W1, b1, W2, b2,
                                           W3, b3, out);
}

// round 16
// speedup vs baseline: 2.7845x; 1.2540x over previous
#include <cuda_runtime.h>
#include <cuda_bf16.h>
#include <cstdint>

// DIN attention. R15: MUFU + occupancy round on top of the R14 dual-HMMA win.
//  - sigmoid via tanh.approx.f32 (1 MUFU instead of 2; XU pipe was ~60% busy
//    and every epilogue chain carried a ~40cyc sigmoid latency).
//  - P2 stride 56->40 u32 (still conflict-free: 40=8 mod 32) -> smem 55.2KB
//    -> 4 CTAs/SM (16 warps), launch_bounds(128,4) (reg cap 128, was 130).
// GEMM1: D1[t,h]=fact@Aw^T (13x10x4), epi: +qW, sigm -> G bf16 (reuses fact).
// GEMM2: D2[t,k]=G@W2 (13x5x5), epi fuses layer-3 + shfl reduce -> scores.
// Softmax + fp32-gmem weighted-sum epilogue unchanged. R14 measured 246.6us.
// (R16 = R15 resubmitted verbatim; R15 bench was a broker acquisition timeout.)

typedef unsigned long long ull;

#define TB 128
#define T_LEN 200
#define THALF 100
#define D_DIM 64
#define H1 80
#define H2 40
#define FST 72      // fact stride u16 (36 w = 4 mod 32: GEMM1 A-frag conflict-free)
#define GST 88      // G stride u16 (44 w = 12 mod 32: GEMM2 A-frag + G-store conflict-free)
#define PST 88      // Pw stride u32 (24 mod 32: B-frag conflict-free)
#define P2ST 40     // P2 stride u32 (8 mod 32: B-frag banks {0,8,16,24}+gid, conflict-free)

struct __align__(16) Smem {
    unsigned short fg[208 * GST];   // 36608B union: fact bf16 [208][72] / G bf16 [208][88]
    unsigned Pw[32 * PST];          // 11264B packed AwT: Pw[d/2][h]
    unsigned P2[40 * P2ST];         // 6400B  packed W2:  P2[h/2][k]
    float qW[H1];
    float q[D_DIM];
    float b2s[H2];
    float W3s[H2];
    float b3s;
    float red[2];
    float scores[T_LEN];
    float partial[128];
};

// sigmoid(x) = 0.5*tanh(x/2) + 0.5  (single MUFU op)
static __device__ __forceinline__ float sigm(float x) {
    float t;
    asm("tanh.approx.f32 %0, %1;" : "=f"(t) : "f"(0.5f * x));
    return fmaf(0.5f, t, 0.5f);
}
// packed bf16x2: lower = a, upper = b
static __device__ __forceinline__ unsigned bf16x2_of(float a, float b) {
    unsigned r;
    asm("cvt.rn.bf16x2.f32 %0, %1, %2;" : "=r"(r) : "f"(b), "f"(a));
    return r;
}
// D += A@B, m16n8k16 bf16 -> f32
static __device__ __forceinline__ void mma16816(
    float& c0, float& c1, float& c2, float& c3,
    unsigned a0, unsigned a1, unsigned a2, unsigned a3,
    unsigned b0, unsigned b1)
{
    asm volatile(
        "mma.sync.aligned.m16n8k16.row.col.f32.bf16.bf16.f32 "
        "{%0,%1,%2,%3}, {%4,%5,%6,%7}, {%8,%9}, {%0,%1,%2,%3};"
        : "+f"(c0), "+f"(c1), "+f"(c2), "+f"(c3)
        : "r"(a0), "r"(a1), "r"(a2), "r"(a3), "r"(b0), "r"(b1));
}

__global__ __launch_bounds__(TB, 4)
void din_attn_kernel(const float* __restrict__ query,
                     const float* __restrict__ fact,
                     const int*   __restrict__ mask,
                     const float* __restrict__ W1,
                     const float* __restrict__ b1,
                     const float* __restrict__ W2,
                     const float* __restrict__ b2,
                     const float* __restrict__ W3,
                     const float* __restrict__ b3,
                     float* __restrict__ out)
{
    extern __shared__ char smem_raw[];
    Smem* sm = (Smem*)smem_raw;
    const int tid  = threadIdx.x;
    const int wid  = tid >> 5;
    const int lane = tid & 31;
    const int gid  = lane >> 2;     // fragment row group
    const int ctid = lane & 3;      // thread-in-group
    const int b    = blockIdx.x;

    if (tid < D_DIM) sm->q[tid] = query[b * D_DIM + tid];
    __syncthreads();

    // ---- Prologue ----
    {   // fact -> bf16 tile [t][d], stride FST
        const float4* src = (const float4*)(fact + (size_t)b * (T_LEN * D_DIM));
        for (int i = tid; i < T_LEN * D_DIM / 4; i += TB) {
            float4 v = src[i];
            int t = i >> 4, d4 = i & 15;
            uint2 pk;
            pk.x = bf16x2_of(v.x, v.y);
            pk.y = bf16x2_of(v.z, v.w);
            *(uint2*)(sm->fg + t * FST + d4 * 4) = pk;
        }
        // zero fact pad rows 200..207
        for (int i = tid; i < 8 * FST / 2; i += TB)
            ((unsigned*)(sm->fg + 200 * FST))[i] = 0;
        // Pw[d2][h] = bf16x2(Aw[h,2d2], Aw[h,2d2+1]);  Aw[h,d] = W1a - W1d + q[d]*W1c
        for (int i = tid; i < 32 * H1; i += TB) {
            int d2 = i / H1, h = i - d2 * H1, d = 2 * d2;
            float a0 = W1[d * H1 + h] - W1[(192 + d) * H1 + h]
                       + sm->q[d] * W1[(128 + d) * H1 + h];
            float a1 = W1[(d + 1) * H1 + h] - W1[(193 + d) * H1 + h]
                       + sm->q[d + 1] * W1[(129 + d) * H1 + h];
            sm->Pw[d2 * PST + h] = bf16x2_of(a0, a1);
        }
        // P2[h2][k] = bf16x2(W2[2h2][k], W2[2h2+1][k])
        for (int i = tid; i < 40 * H2; i += TB) {
            int h2 = i / H2, k = i - h2 * H2;
            sm->P2[h2 * P2ST + k] =
                bf16x2_of(W2[(2 * h2) * H2 + k], W2[(2 * h2 + 1) * H2 + k]);
        }
        if (tid < H1) {
            float a = b1[tid];
            #pragma unroll 4
            for (int d = 0; d < D_DIM; d++)
                a += sm->q[d] * (W1[(64 + d) * H1 + tid] + W1[(192 + d) * H1 + tid]);
            sm->qW[tid] = a;
        }
        if (tid < H2) sm->b2s[tid] = b2[tid];
        if (tid < H2) sm->W3s[tid] = W3[tid];
        if (tid == 0) sm->b3s = b3[0];
    }
    __syncthreads();

    // ---- GEMM1 on tensor cores. Warp w owns m-tiles {w, w+4, w+8, w+12<13}.
    {
        unsigned afr[4][16];
        #pragma unroll
        for (int mi = 0; mi < 4; mi++) {
            int mt = wid + 4 * mi;
            if (mt < 13) {
                const unsigned short* base = sm->fg + (mt * 16 + gid) * FST;
                #pragma unroll
                for (int ks = 0; ks < 4; ks++) {
                    afr[mi][ks * 4 + 0] = *(const unsigned*)(base + ks * 16 + ctid * 2);
                    afr[mi][ks * 4 + 1] = *(const unsigned*)(base + 8 * FST + ks * 16 + ctid * 2);
                    afr[mi][ks * 4 + 2] = *(const unsigned*)(base + ks * 16 + 8 + ctid * 2);
                    afr[mi][ks * 4 + 3] = *(const unsigned*)(base + 8 * FST + ks * 16 + 8 + ctid * 2);
                }
            }
        }
        __syncthreads();            // A frags in regs -> fact region dead, G may overwrite

        for (int n = 0; n < 10; n++) {
            unsigned bfr[4][2];
            #pragma unroll
            for (int ks = 0; ks < 4; ks++) {
                bfr[ks][0] = sm->Pw[(ks * 8 + ctid) * PST + n * 8 + gid];
                bfr[ks][1] = sm->Pw[(ks * 8 + 4 + ctid) * PST + n * 8 + gid];
            }
            const int h0 = n * 8 + ctid * 2;
            float2 qw = *(const float2*)(sm->qW + h0);
            #pragma unroll
            for (int mi = 0; mi < 4; mi++) {
                int mt = wid + 4 * mi;
                if (mt < 13) {
                    float c0 = 0.f, c1 = 0.f, c2 = 0.f, c3 = 0.f;
                    #pragma unroll
                    for (int ks = 0; ks < 4; ks++)
                        mma16816(c0, c1, c2, c3,
                                 afr[mi][ks * 4 + 0], afr[mi][ks * 4 + 1],
                                 afr[mi][ks * 4 + 2], afr[mi][ks * 4 + 3],
                                 bfr[ks][0], bfr[ks][1]);
                    int t0 = mt * 16 + gid, t1 = t0 + 8;
                    *(unsigned*)(sm->fg + t0 * GST + h0) =
                        bf16x2_of(sigm(c0 + qw.x), sigm(c1 + qw.y));
                    if (t1 < T_LEN)
                        *(unsigned*)(sm->fg + t1 * GST + h0) =
                            bf16x2_of(sigm(c2 + qw.x), sigm(c3 + qw.y));
                }
            }
        }
        // zero G pad rows 200..207 (read by GEMM2's last m-tile)
        for (int i = tid; i < 8 * GST / 2; i += TB)
            ((unsigned*)(sm->fg + 200 * GST))[i] = 0;
    }
    __syncthreads();

    // ---- GEMM2 + fused layer-3 ----
    {
        unsigned a2[4][20];         // [mi][ks*4+r], K=80 -> 5 k-steps
        #pragma unroll
        for (int mi = 0; mi < 4; mi++) {
            int mt = wid + 4 * mi;
            if (mt < 13) {
                const unsigned short* base = sm->fg + (mt * 16 + gid) * GST;
                #pragma unroll
                for (int ks = 0; ks < 5; ks++) {
                    a2[mi][ks * 4 + 0] = *(const unsigned*)(base + ks * 16 + ctid * 2);
                    a2[mi][ks * 4 + 1] = *(const unsigned*)(base + 8 * GST + ks * 16 + ctid * 2);
                    a2[mi][ks * 4 + 2] = *(const unsigned*)(base + ks * 16 + 8 + ctid * 2);
                    a2[mi][ks * 4 + 3] = *(const unsigned*)(base + 8 * GST + ks * 16 + 8 + ctid * 2);
                }
            }
        }

        float s0[4] = {0.f, 0.f, 0.f, 0.f};   // score partials, row t0 per mi
        float s1[4] = {0.f, 0.f, 0.f, 0.f};   // row t1 per mi

        for (int n = 0; n < 5; n++) {
            unsigned bfr[5][2];
            #pragma unroll
            for (int ks = 0; ks < 5; ks++) {
                bfr[ks][0] = sm->P2[(ks * 8 + ctid) * P2ST + n * 8 + gid];
                bfr[ks][1] = sm->P2[(ks * 8 + 4 + ctid) * P2ST + n * 8 + gid];
            }
            const int k0 = n * 8 + ctid * 2;
            float2 bb = *(const float2*)(sm->b2s + k0);
            float2 w3 = *(const float2*)(sm->W3s + k0);
            #pragma unroll
            for (int mi = 0; mi < 4; mi++) {
                int mt = wid + 4 * mi;
                if (mt < 13) {
                    float c0 = 0.f, c1 = 0.f, c2 = 0.f, c3 = 0.f;
                    #pragma unroll
                    for (int ks = 0; ks < 5; ks++)
                        mma16816(c0, c1, c2, c3,
                                 a2[mi][ks * 4 + 0], a2[mi][ks * 4 + 1],
                                 a2[mi][ks * 4 + 2], a2[mi][ks * 4 + 3],
                                 bfr[ks][0], bfr[ks][1]);
                    s0[mi] += sigm(c0 + bb.x) * w3.x + sigm(c1 + bb.y) * w3.y;
                    s1[mi] += sigm(c2 + bb.x) * w3.x + sigm(c3 + bb.y) * w3.y;
                }
            }
        }

        // reduce across the 4-lane ctid group (lane = 4*gid + ctid)
        float b3v = sm->b3s;
        #pragma unroll
        for (int mi = 0; mi < 4; mi++) {
            int mt = wid + 4 * mi;
            if (mt < 13) {
                float r0 = s0[mi], r1 = s1[mi];
                r0 += __shfl_xor_sync(0xffffffffu, r0, 1);
                r0 += __shfl_xor_sync(0xffffffffu, r0, 2);
                r1 += __shfl_xor_sync(0xffffffffu, r1, 1);
                r1 += __shfl_xor_sync(0xffffffffu, r1, 2);
                int t0 = mt * 16 + gid, t1 = t0 + 8;
                if (ctid == 0) {
                    sm->scores[t0] = r0 + b3v;
                    if (t1 < T_LEN) sm->scores[t1] = r1 + b3v;
                }
            }
        }
    }
    __syncthreads();

    // ---- Mask + softmax over T ----
    float score0 = 0.0f, score1 = 0.0f;
    int   m0 = 0, m1 = 0;
    float e0 = 0.0f, e1 = 0.0f;
    if (tid < THALF) {
        m0 = mask[b * T_LEN + tid];
        m1 = mask[b * T_LEN + tid + THALF];
        score0 = (m0 == 1) ? sm->scores[tid] : -2147483648.0f;       // NEG_BIG
        score1 = (m1 == 1) ? sm->scores[tid + THALF] : -2147483648.0f;
    }
    __syncthreads();
    if (tid < THALF) {
        sm->scores[tid] = score0;
        sm->scores[tid + THALF] = score1;
    }
    __syncthreads();
    if (tid < 32) {
        float v = -3.4e38f;
        for (int i = tid; i < T_LEN; i += 32) v = fmaxf(v, sm->scores[i]);
        #pragma unroll
        for (int o = 16; o; o >>= 1) v = fmaxf(v, __shfl_xor_sync(0xffffffffu, v, o));
        if (tid == 0) sm->red[0] = v;
    }
    __syncthreads();
    if (tid < THALF) {
        float mx = sm->red[0];
        e0 = __expf(score0 - mx);
        e1 = __expf(score1 - mx);
        sm->scores[tid] = e0;
        sm->scores[tid + THALF] = e1;
    }
    __syncthreads();
    if (tid < 32) {
        float v = 0.0f;
        for (int i = tid; i < T_LEN; i += 32) v += sm->scores[i];
        #pragma unroll
        for (int o = 16; o; o >>= 1) v += __shfl_xor_sync(0xffffffffu, v, o);
        if (tid == 0) sm->red[1] = __fdividef(1.0f, v);
    }
    __syncthreads();
    if (tid < THALF) {
        float inv = sm->red[1];
        sm->scores[tid]         = e0 * inv * (float)m0;
        sm->scores[tid + THALF] = e1 * inv * (float)m1;
    }
    __syncthreads();

    // ---- out[b,d] = sum_t p[t] * fact[t,d]  (fp32 fact from GMEM, coalesced)
    {
        int d = tid & 63, half = tid >> 6;
        const float* fsrc = fact + (size_t)b * (T_LEN * D_DIM) + d;
        float acc = 0.0f;
        int tstart = half * THALF;
        #pragma unroll 4
        for (int tt = tstart; tt < tstart + THALF; tt++)
            acc += sm->scores[tt] * fsrc[(size_t)tt * D_DIM];
        sm->partial[tid] = acc;
    }
    __syncthreads();
    if (tid < D_DIM)
        out[b * D_DIM + tid] = sm->partial[tid] + sm->partial[64 + tid];
}

extern "C" void kernel_launch(void* const* d_in, const int* in_sizes, int n_in,
                              void* d_out, int out_size)
{
    const float* query = (const float*)d_in[0];
    const float* fact  = (const float*)d_in[1];
    const int*   mask  = (const int*)  d_in[2];
    const float* W1    = (const float*)d_in[3];
    const float* b1    = (const float*)d_in[4];
    const float* W2    = (const float*)d_in[5];
    const float* b2    = (const float*)d_in[6];
    const float* W3    = (const float*)d_in[7];
    const float* b3    = (const float*)d_in[8];
    float* out = (float*)d_out;

    const int B = in_sizes[0] / D_DIM;           // 4096
    const int smem_bytes = (int)sizeof(Smem);    // ~55.2 KB -> 4 CTAs/SM
    cudaFuncSetAttribute(din_attn_kernel,
                         cudaFuncAttributeMaxDynamicSharedMemorySize, smem_bytes);
    din_attn_kernel<<<B, TB, smem_bytes>>>(query, fact, mask, W1, b1, W2, b2,
                                           W3, b3, out);
}